// round 12
// baseline (speedup 1.0000x reference)
#include <cuda_runtime.h>
#include <cuda_bf16.h>
#include <mma.h>
#include <cstdint>

using namespace nvcuda;

// Problem constants
constexpr int kB = 2;
constexpr int kT = 2048;
constexpr int kC = 1024;
constexpr int kH = 16;
constexpr int kD = 64;
constexpr int kM = kB * kT;        // 4096
constexpr int kNQKV = 3 * kC;      // 3072
constexpr int kBH = kB * kH;       // 32

// Scratch (static device globals — no allocation allowed)
__device__ float g_qkv[kM * kNQKV];
__device__ __nv_bfloat16 g_qbh[kBH * kT * kD], g_qbl[kBH * kT * kD];
__device__ __nv_bfloat16 g_kbh[kBH * kT * kD], g_kbl[kBH * kT * kD];
__device__ __nv_bfloat16 g_vbh[kBH * kT * kD], g_vbl[kBH * kT * kD];
// split-bf16 GEMM operands
__device__ __nv_bfloat16 g_xh[kM * kC],     g_xl[kM * kC];
__device__ __nv_bfloat16 g_wqh[kNQKV * kC], g_wql[kNQKV * kC];
__device__ __nv_bfloat16 g_ath[kM * kC],    g_atl[kM * kC];
__device__ __nv_bfloat16 g_woh[kC * kC],    g_wol[kC * kC];

// ===========================================================================
// helpers
// ===========================================================================
__device__ __forceinline__ uint32_t smem_u32(const void* p) {
    uint32_t a;
    asm("{ .reg .u64 t; cvta.to.shared.u64 t, %1; cvt.u32.u64 %0, t; }"
        : "=r"(a) : "l"(p));
    return a;
}
__device__ __forceinline__ void cp_async16(void* sdst, const void* gsrc) {
    asm volatile("cp.async.cg.shared.global [%0], [%1], 16;"
                 :: "r"(smem_u32(sdst)), "l"(gsrc) : "memory");
}
__device__ __forceinline__ void cp_commit() {
    asm volatile("cp.async.commit_group;" ::: "memory");
}
__device__ __forceinline__ void cp_wait1() {
    asm volatile("cp.async.wait_group 1;" ::: "memory");
}
__device__ __forceinline__ float fast_exp2(float x) {
    float y;
    asm("ex2.approx.ftz.f32 %0, %1;" : "=f"(y) : "f"(x));
    return y;
}

// ===========================================================================
// FUSED split-bf16 GEMM-NT via WMMA.
// Per 32-K chunk, stage (Ah, Al, Bh, Bl) once and accumulate all three
// products Ah*Bh + Ah*Bl + Al*Bh into the same fp32 fragments:
//   - 1/3 of the sync iterations of the 3-pass version
//   - 2/3 of the global staging traffic, 2/3 of the fragment loads
// 3-stage cp.async pipeline (120KB smem, 1 CTA/SM), 8 warps, tile 128x128.
// Products ordered hh->hl->lh with all fragments resident so accumulator
// reuse distance is 8 MMAs (no dependency stalls).
// ===========================================================================
constexpr int kLds = 40;                       // bf16 row stride (80B)
constexpr int kTile = 128 * kLds;              // one 128x32 tile (bf16 elems)
constexpr int kStageElems = 4 * kTile;         // Ah,Al,Bh,Bl
constexpr int kGemmSmem = 3 * kStageElems * 2; // 122880 bytes

__global__ __launch_bounds__(256, 1) void gemm_wmma_fused(
    const __nv_bfloat16* __restrict__ Ah, const __nv_bfloat16* __restrict__ Al,
    const __nv_bfloat16* __restrict__ Bh, const __nv_bfloat16* __restrict__ Bl,
    float* __restrict__ Cm, int Nd, int Kd)
{
    extern __shared__ __nv_bfloat16 sm[];

    const int tid = threadIdx.x;
    const int warp = tid >> 5;
    const int wm = warp & 3;            // 4 warps along M (32 rows each)
    const int wn = warp >> 2;           // 2 warps along N (64 cols each)
    const int row0 = blockIdx.y * 128;
    const int col0 = blockIdx.x * 128;

    const int nchunk = Kd >> 5;

    auto issue = [&](int it) {
        const int kc = it << 5;
        __nv_bfloat16* st = sm + (it % 3) * kStageElems;
#pragma unroll
        for (int s = 0; s < 2; s++) {
            int idx = tid + s * 256;         // 0..511
            int r = idx >> 2;                // row 0..127
            int c8 = (idx & 3) * 8;          // bf16 col 0/8/16/24
            size_t ga = (size_t)(row0 + r) * Kd + kc + c8;
            size_t gb = (size_t)(col0 + r) * Kd + kc + c8;
            int so = r * kLds + c8;
            cp_async16(&st[so],             Ah + ga);
            cp_async16(&st[kTile + so],     Al + ga);
            cp_async16(&st[2 * kTile + so], Bh + gb);
            cp_async16(&st[3 * kTile + so], Bl + gb);
        }
    };

    wmma::fragment<wmma::accumulator, 16, 16, 16, float> acc[2][4];
#pragma unroll
    for (int i = 0; i < 2; i++)
#pragma unroll
        for (int j = 0; j < 4; j++)
            wmma::fill_fragment(acc[i][j], 0.f);

    issue(0); cp_commit();
    issue(1); cp_commit();

    for (int it = 0; it < nchunk; it++) {
        cp_wait1();
        __syncthreads();
        if (it + 2 < nchunk) issue(it + 2);   // buffer (it+2)%3 freed by sync
        cp_commit();

        const __nv_bfloat16* Ash = sm + (it % 3) * kStageElems;
        const __nv_bfloat16* Asl = Ash + kTile;
        const __nv_bfloat16* Bsh = Ash + 2 * kTile;
        const __nv_bfloat16* Bsl = Ash + 3 * kTile;

#pragma unroll
        for (int k2 = 0; k2 < 2; k2++) {
            wmma::fragment<wmma::matrix_a, 16, 16, 16, __nv_bfloat16,
                           wmma::row_major> ah[2], al[2];
            wmma::fragment<wmma::matrix_b, 16, 16, 16, __nv_bfloat16,
                           wmma::col_major> bh[4], bl[4];
#pragma unroll
            for (int i = 0; i < 2; i++) {
                wmma::load_matrix_sync(
                    ah[i], &Ash[(wm * 32 + i * 16) * kLds + k2 * 16], kLds);
                wmma::load_matrix_sync(
                    al[i], &Asl[(wm * 32 + i * 16) * kLds + k2 * 16], kLds);
            }
#pragma unroll
            for (int j = 0; j < 4; j++) {
                wmma::load_matrix_sync(
                    bh[j], &Bsh[(wn * 64 + j * 16) * kLds + k2 * 16], kLds);
                wmma::load_matrix_sync(
                    bl[j], &Bsl[(wn * 64 + j * 16) * kLds + k2 * 16], kLds);
            }
            // product hh
#pragma unroll
            for (int i = 0; i < 2; i++)
#pragma unroll
                for (int j = 0; j < 4; j++)
                    wmma::mma_sync(acc[i][j], ah[i], bh[j], acc[i][j]);
            // product hl
#pragma unroll
            for (int i = 0; i < 2; i++)
#pragma unroll
                for (int j = 0; j < 4; j++)
                    wmma::mma_sync(acc[i][j], ah[i], bl[j], acc[i][j]);
            // product lh
#pragma unroll
            for (int i = 0; i < 2; i++)
#pragma unroll
                for (int j = 0; j < 4; j++)
                    wmma::mma_sync(acc[i][j], al[i], bh[j], acc[i][j]);
        }
    }

#pragma unroll
    for (int i = 0; i < 2; i++)
#pragma unroll
        for (int j = 0; j < 4; j++) {
            float* cp = Cm + (size_t)(row0 + wm * 32 + i * 16) * Nd
                           + col0 + wn * 64 + j * 16;
            wmma::store_matrix_sync(cp, acc[i][j], Nd, wmma::mem_row_major);
        }
}

// ===========================================================================
// fp32 -> (hi, lo) bf16 split, 4 elems/thread
// ===========================================================================
__global__ void cvt_hilo4(const float* __restrict__ s,
                          __nv_bfloat16* __restrict__ hi,
                          __nv_bfloat16* __restrict__ lo, int n4)
{
    int i = blockIdx.x * blockDim.x + threadIdx.x;
    if (i < n4) {
        float4 v = ((const float4*)s)[i];
        __nv_bfloat16 h0 = __float2bfloat16(v.x);
        __nv_bfloat16 h1 = __float2bfloat16(v.y);
        __nv_bfloat16 h2 = __float2bfloat16(v.z);
        __nv_bfloat16 h3 = __float2bfloat16(v.w);
        __nv_bfloat162* hp = (__nv_bfloat162*)(hi) + 2 * i;
        __nv_bfloat162* lp = (__nv_bfloat162*)(lo) + 2 * i;
        hp[0] = __nv_bfloat162(h0, h1);
        hp[1] = __nv_bfloat162(h2, h3);
        lp[0] = __nv_bfloat162(__float2bfloat16(v.x - __bfloat162float(h0)),
                               __float2bfloat16(v.y - __bfloat162float(h1)));
        lp[1] = __nv_bfloat162(__float2bfloat16(v.z - __bfloat162float(h2)),
                               __float2bfloat16(v.w - __bfloat162float(h3)));
    }
}

// ===========================================================================
// RoPE + split qkv -> Q/K (roped), V, all hi/lo bf16 in [b,h,t,d]
// ===========================================================================
__device__ __forceinline__ void split_store(__nv_bfloat16* hi, __nv_bfloat16* lo,
                                            int o, float v) {
    __nv_bfloat16 h = __float2bfloat16(v);
    hi[o] = h;
    lo[o] = __float2bfloat16(v - __bfloat162float(h));
}

__global__ void rope_split(const float* __restrict__ qkv,
                           const float* __restrict__ cosp,
                           const float* __restrict__ sinp)
{
    int idx = blockIdx.x * blockDim.x + threadIdx.x;
    int dd = idx & 31;
    int rest = idx >> 5;
    int t = rest & (kT - 1);
    rest >>= 11;
    int h = rest & (kH - 1);
    int b = rest >> 4;

    int base = (b * kT + t) * kNQKV + h * kD;
    float c  = cosp[t * 32 + dd];
    float sn = sinp[t * 32 + dd];

    float q1 = qkv[base + dd];
    float q2 = qkv[base + 32 + dd];
    float k1 = qkv[base + kC + dd];
    float k2 = qkv[base + kC + 32 + dd];
    float v1 = qkv[base + 2 * kC + dd];
    float v2 = qkv[base + 2 * kC + 32 + dd];

    int o = ((b * kH + h) * kT + t) * kD + dd;
    split_store(g_qbh, g_qbl, o,      q1 * c - q2 * sn);
    split_store(g_qbh, g_qbl, o + 32, q2 * c + q1 * sn);
    split_store(g_kbh, g_kbl, o,      k1 * c - k2 * sn);
    split_store(g_kbh, g_kbl, o + 32, k2 * c + k1 * sn);
    split_store(g_vbh, g_vbl, o,      v1);
    split_store(g_vbh, g_vbl, o + 32, v2);
}

// ===========================================================================
// Split-bf16 WMMA flash attention (round-11 proven): 64 q/block, 64-key
// tiles, 8 warps. S = Qh Kh + Qh Kl + Ql Kh -> masked exp (max-free) ->
// P hi/lo -> O += Ph Vh + Ph Vl + Pl Vh. O frags persist across tiles.
// ===========================================================================
constexpr int kAttnSmem = 8 * 64 * 72 * 2 + 64 * 68 * 4 + 256 * 4; // 92160

__global__ __launch_bounds__(256, 2) void flash_wmma2()
{
    extern __shared__ char smraw[];
    __nv_bfloat16* Qh = (__nv_bfloat16*)smraw;            // each [64][72]
    __nv_bfloat16* Ql  = Qh  + 64 * 72;
    __nv_bfloat16* Kh  = Ql  + 64 * 72;
    __nv_bfloat16* Kl  = Kh  + 64 * 72;
    __nv_bfloat16* Vh  = Kl  + 64 * 72;
    __nv_bfloat16* Vl  = Vh  + 64 * 72;
    __nv_bfloat16* Pbh = Vl  + 64 * 72;
    __nv_bfloat16* Pbl = Pbh + 64 * 72;
    float* Ps = (float*)(Pbl + 64 * 72);                  // [64][68]
    float* lp = Ps + 64 * 68;                             // [4][64]

    const int tid = threadIdx.x, warp = tid >> 5;
    const int wm = warp & 3, wn = warp >> 2;
    const int bh = blockIdx.y;
    const int q0 = blockIdx.x * 64;
    const float L2E = 1.4426950408889634f;

    const size_t hb = (size_t)bh * kT * kD;

    lp[tid] = 0.f;
#pragma unroll
    for (int s = 0; s < 2; s++) {
        int idx = tid + s * 256;
        int r = idx >> 3, c8 = (idx & 7) * 8;
        *(uint4*)&Qh[r * 72 + c8] = *(const uint4*)(g_qbh + hb + (q0 + r) * kD + c8);
        *(uint4*)&Ql[r * 72 + c8] = *(const uint4*)(g_qbl + hb + (q0 + r) * kD + c8);
    }

    wmma::fragment<wmma::accumulator, 16, 16, 16, float> oacc[2];
#pragma unroll
    for (int j = 0; j < 2; j++) wmma::fill_fragment(oacc[j], 0.f);

    const int ntiles = blockIdx.x + 1;
    for (int kt = 0; kt < ntiles; kt++) {
        const int kb = kt * 64;
        __syncthreads();
#pragma unroll
        for (int s = 0; s < 2; s++) {
            int idx = tid + s * 256;
            int r = idx >> 3, c8 = (idx & 7) * 8;
            size_t g = hb + (size_t)(kb + r) * kD + c8;
            *(uint4*)&Kh[r * 72 + c8] = *(const uint4*)(g_kbh + g);
            *(uint4*)&Kl[r * 72 + c8] = *(const uint4*)(g_kbl + g);
            *(uint4*)&Vh[r * 72 + c8] = *(const uint4*)(g_vbh + g);
            *(uint4*)&Vl[r * 72 + c8] = *(const uint4*)(g_vbl + g);
        }
        __syncthreads();

        // ---- S = Qh Kh + Qh Kl + Ql Kh  (warp tile 16x32)
        wmma::fragment<wmma::accumulator, 16, 16, 16, float> sacc[2];
#pragma unroll
        for (int j = 0; j < 2; j++) wmma::fill_fragment(sacc[j], 0.f);
#pragma unroll
        for (int ks = 0; ks < 4; ks++) {
            wmma::fragment<wmma::matrix_a, 16, 16, 16, __nv_bfloat16,
                           wmma::row_major> ah, al;
            wmma::load_matrix_sync(ah, &Qh[(wm * 16) * 72 + ks * 16], 72);
            wmma::load_matrix_sync(al, &Ql[(wm * 16) * 72 + ks * 16], 72);
#pragma unroll
            for (int j = 0; j < 2; j++) {
                wmma::fragment<wmma::matrix_b, 16, 16, 16, __nv_bfloat16,
                               wmma::col_major> bhf, blf;
                wmma::load_matrix_sync(
                    bhf, &Kh[(wn * 32 + j * 16) * 72 + ks * 16], 72);
                wmma::load_matrix_sync(
                    blf, &Kl[(wn * 32 + j * 16) * 72 + ks * 16], 72);
                wmma::mma_sync(sacc[j], ah, bhf, sacc[j]);
                wmma::mma_sync(sacc[j], ah, blf, sacc[j]);
                wmma::mma_sync(sacc[j], al, bhf, sacc[j]);
            }
        }
#pragma unroll
        for (int j = 0; j < 2; j++)
            wmma::store_matrix_sync(&Ps[(wm * 16) * 68 + wn * 32 + j * 16],
                                    sacc[j], 68, wmma::mem_row_major);
        __syncthreads();

        // ---- masked exp (max-free), row-partial normalizer, P -> hi/lo bf16
        {
            int r = tid >> 2, g = tid & 3;
            int qpos = q0 + r;
            float lsum = 0.f;
#pragma unroll
            for (int i = 0; i < 16; i++) {
                int c = g * 16 + i;
                float s = Ps[r * 68 + c] * 0.125f;
                float p = fast_exp2(s * L2E);
                if (kb + c > qpos) p = 0.f;
                lsum += p;
                __nv_bfloat16 ph = __float2bfloat16(p);
                Pbh[r * 72 + c] = ph;
                Pbl[r * 72 + c] = __float2bfloat16(p - __bfloat162float(ph));
            }
            lp[g * 64 + r] += lsum;
        }
        __syncthreads();

        // ---- O += Ph Vh + Ph Vl + Pl Vh
#pragma unroll
        for (int ks = 0; ks < 4; ks++) {
            wmma::fragment<wmma::matrix_a, 16, 16, 16, __nv_bfloat16,
                           wmma::row_major> ah, al;
            wmma::load_matrix_sync(ah, &Pbh[(wm * 16) * 72 + ks * 16], 72);
            wmma::load_matrix_sync(al, &Pbl[(wm * 16) * 72 + ks * 16], 72);
#pragma unroll
            for (int j = 0; j < 2; j++) {
                wmma::fragment<wmma::matrix_b, 16, 16, 16, __nv_bfloat16,
                               wmma::row_major> bhf, blf;
                wmma::load_matrix_sync(
                    bhf, &Vh[(ks * 16) * 72 + wn * 32 + j * 16], 72);
                wmma::load_matrix_sync(
                    blf, &Vl[(ks * 16) * 72 + wn * 32 + j * 16], 72);
                wmma::mma_sync(oacc[j], ah, bhf, oacc[j]);
                wmma::mma_sync(oacc[j], ah, blf, oacc[j]);
                wmma::mma_sync(oacc[j], al, bhf, oacc[j]);
            }
        }
    }

    // ---- epilogue: O -> smem, normalize rows, write bf16 hi/lo
    __syncthreads();
#pragma unroll
    for (int j = 0; j < 2; j++)
        wmma::store_matrix_sync(&Ps[(wm * 16) * 68 + wn * 32 + j * 16],
                                oacc[j], 68, wmma::mem_row_major);
    __syncthreads();
    {
        int r = tid >> 2, g = tid & 3;
        float lrow = lp[r] + lp[64 + r] + lp[128 + r] + lp[192 + r];
        float inv = 1.f / lrow;
        const int b = bh >> 4, h = bh & 15;
        size_t base = (size_t)(b * kT + q0 + r) * kC + h * kD;
#pragma unroll
        for (int i = 0; i < 16; i++) {
            int c = g * 16 + i;
            float v = Ps[r * 68 + c] * inv;
            __nv_bfloat16 hv = __float2bfloat16(v);
            g_ath[base + c] = hv;
            g_atl[base + c] = __float2bfloat16(v - __bfloat162float(hv));
        }
    }
}

// ===========================================================================
extern "C" void kernel_launch(void* const* d_in, const int* in_sizes, int n_in,
                              void* d_out, int out_size)
{
    const float* x    = (const float*)d_in[0];
    const float* cosp = (const float*)d_in[1];
    const float* sinp = (const float*)d_in[2];
    // d_in[3] = mask (implicit causal)
    const float* Wqkv = (const float*)d_in[4];
    const float* Wout = (const float*)d_in[5];
    float* out = (float*)d_out;

    float* pqkv;
    __nv_bfloat16 *pxh, *pxl, *pwqh, *pwql, *path, *patl, *pwoh, *pwol;
    cudaGetSymbolAddress((void**)&pqkv, g_qkv);
    cudaGetSymbolAddress((void**)&pxh, g_xh);
    cudaGetSymbolAddress((void**)&pxl, g_xl);
    cudaGetSymbolAddress((void**)&pwqh, g_wqh);
    cudaGetSymbolAddress((void**)&pwql, g_wql);
    cudaGetSymbolAddress((void**)&path, g_ath);
    cudaGetSymbolAddress((void**)&patl, g_atl);
    cudaGetSymbolAddress((void**)&pwoh, g_woh);
    cudaGetSymbolAddress((void**)&pwol, g_wol);

    cudaFuncSetAttribute(gemm_wmma_fused,
                         cudaFuncAttributeMaxDynamicSharedMemorySize, kGemmSmem);
    cudaFuncSetAttribute(flash_wmma2,
                         cudaFuncAttributeMaxDynamicSharedMemorySize, kAttnSmem);

    // 1. split inputs/weights to bf16 hi/lo
    cvt_hilo4<<<(kM * kC / 4 + 255) / 256, 256>>>(x, pxh, pxl, kM * kC / 4);
    cvt_hilo4<<<(kNQKV * kC / 4 + 255) / 256, 256>>>(Wqkv, pwqh, pwql, kNQKV * kC / 4);
    cvt_hilo4<<<(kC * kC / 4 + 255) / 256, 256>>>(Wout, pwoh, pwol, kC * kC / 4);

    // 2. QKV projection (fused split-bf16 WMMA)
    gemm_wmma_fused<<<dim3(kNQKV / 128, kM / 128), 256, kGemmSmem>>>(
        pxh, pxl, pwqh, pwql, pqkv, kNQKV, kC);

    // 3. RoPE + head split -> hi/lo bf16 Q/K/V
    rope_split<<<(kBH * kT * 32) / 256, 256>>>(pqkv, cosp, sinp);

    // 4. split-bf16 WMMA causal attention (writes bf16 hi/lo directly)
    flash_wmma2<<<dim3(kT / 64, kBH), 256, kAttnSmem>>>();

    // 5. output projection (fused split-bf16 WMMA)
    gemm_wmma_fused<<<dim3(kC / 128, kM / 128), 256, kGemmSmem>>>(
        path, patl, pwoh, pwol, out, kC, kC);
}

// round 13
// speedup vs baseline: 1.3430x; 1.3430x over previous
#include <cuda_runtime.h>
#include <cuda_bf16.h>
#include <cuda_fp16.h>
#include <mma.h>
#include <cstdint>

using namespace nvcuda;

// Problem constants
constexpr int kB = 2;
constexpr int kT = 2048;
constexpr int kC = 1024;
constexpr int kH = 16;
constexpr int kD = 64;
constexpr int kM = kB * kT;        // 4096
constexpr int kNQKV = 3 * kC;      // 3072
constexpr int kBH = kB * kH;       // 32

// Scratch (static device globals — no allocation allowed)
__device__ float g_qkv[kM * kNQKV];
__device__ __nv_bfloat16 g_qbh[kBH * kT * kD], g_qbl[kBH * kT * kD];
__device__ __nv_bfloat16 g_kbh[kBH * kT * kD], g_kbl[kBH * kT * kD];
__device__ __nv_bfloat16 g_vbh[kBH * kT * kD], g_vbl[kBH * kT * kD];
// fp16 QKV-GEMM operands
__device__ __half g_xf[kM * kC];
__device__ __half g_wqf[kNQKV * kC];
// split-bf16 out-proj operands
__device__ __nv_bfloat16 g_ath[kM * kC], g_atl[kM * kC];
__device__ __nv_bfloat16 g_woh[kC * kC], g_wol[kC * kC];

// ===========================================================================
// helpers
// ===========================================================================
__device__ __forceinline__ uint32_t smem_u32(const void* p) {
    uint32_t a;
    asm("{ .reg .u64 t; cvta.to.shared.u64 t, %1; cvt.u32.u64 %0, t; }"
        : "=r"(a) : "l"(p));
    return a;
}
__device__ __forceinline__ void cp_async16(void* sdst, const void* gsrc) {
    asm volatile("cp.async.cg.shared.global [%0], [%1], 16;"
                 :: "r"(smem_u32(sdst)), "l"(gsrc) : "memory");
}
__device__ __forceinline__ void cp_commit() {
    asm volatile("cp.async.commit_group;" ::: "memory");
}
__device__ __forceinline__ void cp_wait2() {
    asm volatile("cp.async.wait_group 2;" ::: "memory");
}
__device__ __forceinline__ float fast_exp2(float x) {
    float y;
    asm("ex2.approx.ftz.f32 %0, %1;" : "=f"(y) : "f"(x));
    return y;
}

// ===========================================================================
// Single-pass FP16 GEMM-NT via WMMA (for QKV projection — error attenuated
// downstream through softmax averaging). Round-5 proven skeleton: 128x128
// tile, BK=32, 8 warps (32x64 warp tile), 4-stage cp.async, 2 CTA/SM.
// ===========================================================================
constexpr int kLds = 40;                        // fp16 row stride (80B)
constexpr int kStageElems = 2 * 128 * kLds;     // A + B per stage
constexpr int kGemmSmem16 = 4 * kStageElems * 2;

__global__ __launch_bounds__(256) void gemm_wmma_fp16(
    const __half* __restrict__ A, const __half* __restrict__ Bm,
    float* __restrict__ Cm, int Nd, int Kd)
{
    extern __shared__ __half smh[];

    const int tid = threadIdx.x;
    const int warp = tid >> 5;
    const int wm = warp & 3;
    const int wn = warp >> 2;
    const int row0 = blockIdx.y * 128;
    const int col0 = blockIdx.x * 128;

    const int nchunk = Kd >> 5;

    auto issue = [&](int it) {
        const int kc = it << 5;
        __half* As = smh + (it & 3) * kStageElems;
        __half* Bs = As + 128 * kLds;
#pragma unroll
        for (int s = 0; s < 2; s++) {
            int idx = tid + s * 256;
            int r = idx >> 2;
            int c8 = (idx & 3) * 8;
            cp_async16(&As[r * kLds + c8], A + (size_t)(row0 + r) * Kd + kc + c8);
            cp_async16(&Bs[r * kLds + c8], Bm + (size_t)(col0 + r) * Kd + kc + c8);
        }
    };

    wmma::fragment<wmma::accumulator, 16, 16, 16, float> acc[2][4];
#pragma unroll
    for (int i = 0; i < 2; i++)
#pragma unroll
        for (int j = 0; j < 4; j++)
            wmma::fill_fragment(acc[i][j], 0.f);

    issue(0); cp_commit();
    issue(1); cp_commit();
    issue(2); cp_commit();

    for (int it = 0; it < nchunk; it++) {
        cp_wait2();
        __syncthreads();
        if (it + 3 < nchunk) issue(it + 3);
        cp_commit();

        const __half* As = smh + (it & 3) * kStageElems;
        const __half* Bs = As + 128 * kLds;
#pragma unroll
        for (int k2 = 0; k2 < 2; k2++) {
            wmma::fragment<wmma::matrix_a, 16, 16, 16, __half,
                           wmma::row_major> af[2];
            wmma::fragment<wmma::matrix_b, 16, 16, 16, __half,
                           wmma::col_major> bf[4];
#pragma unroll
            for (int i = 0; i < 2; i++)
                wmma::load_matrix_sync(
                    af[i], &As[(wm * 32 + i * 16) * kLds + k2 * 16], kLds);
#pragma unroll
            for (int j = 0; j < 4; j++)
                wmma::load_matrix_sync(
                    bf[j], &Bs[(wn * 64 + j * 16) * kLds + k2 * 16], kLds);
#pragma unroll
            for (int i = 0; i < 2; i++)
#pragma unroll
                for (int j = 0; j < 4; j++)
                    wmma::mma_sync(acc[i][j], af[i], bf[j], acc[i][j]);
        }
    }

#pragma unroll
    for (int i = 0; i < 2; i++)
#pragma unroll
        for (int j = 0; j < 4; j++) {
            float* cp = Cm + (size_t)(row0 + wm * 32 + i * 16) * Nd
                           + col0 + wn * 64 + j * 16;
            wmma::store_matrix_sync(cp, acc[i][j], Nd, wmma::mem_row_major);
        }
}

// ===========================================================================
// 3-pass split-bf16 GEMM-NT via WMMA (round-5 proven) — out-projection,
// where precision hits the output directly.
// ===========================================================================
constexpr int kGemmSmemBf = 4 * kStageElems * 2;

__global__ __launch_bounds__(256) void gemm_wmma_split(
    const __nv_bfloat16* __restrict__ Ah, const __nv_bfloat16* __restrict__ Al,
    const __nv_bfloat16* __restrict__ Bh, const __nv_bfloat16* __restrict__ Bl,
    float* __restrict__ Cm, int Nd, int Kd)
{
    extern __shared__ __nv_bfloat16 sm[];

    const int tid = threadIdx.x;
    const int warp = tid >> 5;
    const int wm = warp & 3;
    const int wn = warp >> 2;
    const int row0 = blockIdx.y * 128;
    const int col0 = blockIdx.x * 128;

    const int nchunk = Kd >> 5;
    const int total = 3 * nchunk;

    auto issue = [&](int it) {
        const int pass = it / nchunk;
        const int kc = (it - pass * nchunk) << 5;
        const __nv_bfloat16* Ap = (pass == 2) ? Al : Ah;
        const __nv_bfloat16* Bp = (pass == 1) ? Bl : Bh;
        __nv_bfloat16* As = sm + (it & 3) * kStageElems;
        __nv_bfloat16* Bs = As + 128 * kLds;
#pragma unroll
        for (int s = 0; s < 2; s++) {
            int idx = tid + s * 256;
            int r = idx >> 2;
            int c8 = (idx & 3) * 8;
            cp_async16(&As[r * kLds + c8], Ap + (size_t)(row0 + r) * Kd + kc + c8);
            cp_async16(&Bs[r * kLds + c8], Bp + (size_t)(col0 + r) * Kd + kc + c8);
        }
    };

    wmma::fragment<wmma::accumulator, 16, 16, 16, float> acc[2][4];
#pragma unroll
    for (int i = 0; i < 2; i++)
#pragma unroll
        for (int j = 0; j < 4; j++)
            wmma::fill_fragment(acc[i][j], 0.f);

    issue(0); cp_commit();
    issue(1); cp_commit();
    issue(2); cp_commit();

    for (int it = 0; it < total; it++) {
        cp_wait2();
        __syncthreads();
        if (it + 3 < total) issue(it + 3);
        cp_commit();

        const __nv_bfloat16* As = sm + (it & 3) * kStageElems;
        const __nv_bfloat16* Bs = As + 128 * kLds;
#pragma unroll
        for (int k2 = 0; k2 < 2; k2++) {
            wmma::fragment<wmma::matrix_a, 16, 16, 16, __nv_bfloat16,
                           wmma::row_major> af[2];
            wmma::fragment<wmma::matrix_b, 16, 16, 16, __nv_bfloat16,
                           wmma::col_major> bf[4];
#pragma unroll
            for (int i = 0; i < 2; i++)
                wmma::load_matrix_sync(
                    af[i], &As[(wm * 32 + i * 16) * kLds + k2 * 16], kLds);
#pragma unroll
            for (int j = 0; j < 4; j++)
                wmma::load_matrix_sync(
                    bf[j], &Bs[(wn * 64 + j * 16) * kLds + k2 * 16], kLds);
#pragma unroll
            for (int i = 0; i < 2; i++)
#pragma unroll
                for (int j = 0; j < 4; j++)
                    wmma::mma_sync(acc[i][j], af[i], bf[j], acc[i][j]);
        }
    }

#pragma unroll
    for (int i = 0; i < 2; i++)
#pragma unroll
        for (int j = 0; j < 4; j++) {
            float* cp = Cm + (size_t)(row0 + wm * 32 + i * 16) * Nd
                           + col0 + wn * 64 + j * 16;
            wmma::store_matrix_sync(cp, acc[i][j], Nd, wmma::mem_row_major);
        }
}

// ===========================================================================
// converters
// ===========================================================================
__global__ void cvt_fp16_4(const float* __restrict__ s,
                           __half* __restrict__ d, int n4)
{
    int i = blockIdx.x * blockDim.x + threadIdx.x;
    if (i < n4) {
        float4 v = ((const float4*)s)[i];
        __half2* dp = (__half2*)(d) + 2 * i;
        dp[0] = __floats2half2_rn(v.x, v.y);
        dp[1] = __floats2half2_rn(v.z, v.w);
    }
}

__global__ void cvt_hilo4(const float* __restrict__ s,
                          __nv_bfloat16* __restrict__ hi,
                          __nv_bfloat16* __restrict__ lo, int n4)
{
    int i = blockIdx.x * blockDim.x + threadIdx.x;
    if (i < n4) {
        float4 v = ((const float4*)s)[i];
        __nv_bfloat16 h0 = __float2bfloat16(v.x);
        __nv_bfloat16 h1 = __float2bfloat16(v.y);
        __nv_bfloat16 h2 = __float2bfloat16(v.z);
        __nv_bfloat16 h3 = __float2bfloat16(v.w);
        __nv_bfloat162* hp = (__nv_bfloat162*)(hi) + 2 * i;
        __nv_bfloat162* lp = (__nv_bfloat162*)(lo) + 2 * i;
        hp[0] = __nv_bfloat162(h0, h1);
        hp[1] = __nv_bfloat162(h2, h3);
        lp[0] = __nv_bfloat162(__float2bfloat16(v.x - __bfloat162float(h0)),
                               __float2bfloat16(v.y - __bfloat162float(h1)));
        lp[1] = __nv_bfloat162(__float2bfloat16(v.z - __bfloat162float(h2)),
                               __float2bfloat16(v.w - __bfloat162float(h3)));
    }
}

// ===========================================================================
// RoPE + split qkv -> Q/K (roped), V, all hi/lo bf16 in [b,h,t,d]
// ===========================================================================
__device__ __forceinline__ void split_store(__nv_bfloat16* hi, __nv_bfloat16* lo,
                                            int o, float v) {
    __nv_bfloat16 h = __float2bfloat16(v);
    hi[o] = h;
    lo[o] = __float2bfloat16(v - __bfloat162float(h));
}

__global__ void rope_split(const float* __restrict__ qkv,
                           const float* __restrict__ cosp,
                           const float* __restrict__ sinp)
{
    int idx = blockIdx.x * blockDim.x + threadIdx.x;
    int dd = idx & 31;
    int rest = idx >> 5;
    int t = rest & (kT - 1);
    rest >>= 11;
    int h = rest & (kH - 1);
    int b = rest >> 4;

    int base = (b * kT + t) * kNQKV + h * kD;
    float c  = cosp[t * 32 + dd];
    float sn = sinp[t * 32 + dd];

    float q1 = qkv[base + dd];
    float q2 = qkv[base + 32 + dd];
    float k1 = qkv[base + kC + dd];
    float k2 = qkv[base + kC + 32 + dd];
    float v1 = qkv[base + 2 * kC + dd];
    float v2 = qkv[base + 2 * kC + 32 + dd];

    int o = ((b * kH + h) * kT + t) * kD + dd;
    split_store(g_qbh, g_qbl, o,      q1 * c - q2 * sn);
    split_store(g_qbh, g_qbl, o + 32, q2 * c + q1 * sn);
    split_store(g_kbh, g_kbl, o,      k1 * c - k2 * sn);
    split_store(g_kbh, g_kbl, o + 32, k2 * c + k1 * sn);
    split_store(g_vbh, g_vbl, o,      v1);
    split_store(g_vbh, g_vbl, o + 32, v2);
}

// ===========================================================================
// Split-bf16 WMMA flash attention (round-11 proven): 64 q/block, 64-key
// tiles, 8 warps.
// ===========================================================================
constexpr int kAttnSmem = 8 * 64 * 72 * 2 + 64 * 68 * 4 + 256 * 4; // 92160

__global__ __launch_bounds__(256, 2) void flash_wmma2()
{
    extern __shared__ char smraw[];
    __nv_bfloat16* Qh = (__nv_bfloat16*)smraw;            // each [64][72]
    __nv_bfloat16* Ql  = Qh  + 64 * 72;
    __nv_bfloat16* Kh  = Ql  + 64 * 72;
    __nv_bfloat16* Kl  = Kh  + 64 * 72;
    __nv_bfloat16* Vh  = Kl  + 64 * 72;
    __nv_bfloat16* Vl  = Vh  + 64 * 72;
    __nv_bfloat16* Pbh = Vl  + 64 * 72;
    __nv_bfloat16* Pbl = Pbh + 64 * 72;
    float* Ps = (float*)(Pbl + 64 * 72);                  // [64][68]
    float* lp = Ps + 64 * 68;                             // [4][64]

    const int tid = threadIdx.x, warp = tid >> 5;
    const int wm = warp & 3, wn = warp >> 2;
    const int bh = blockIdx.y;
    const int q0 = blockIdx.x * 64;
    const float L2E = 1.4426950408889634f;

    const size_t hb = (size_t)bh * kT * kD;

    lp[tid] = 0.f;
#pragma unroll
    for (int s = 0; s < 2; s++) {
        int idx = tid + s * 256;
        int r = idx >> 3, c8 = (idx & 7) * 8;
        *(uint4*)&Qh[r * 72 + c8] = *(const uint4*)(g_qbh + hb + (q0 + r) * kD + c8);
        *(uint4*)&Ql[r * 72 + c8] = *(const uint4*)(g_qbl + hb + (q0 + r) * kD + c8);
    }

    wmma::fragment<wmma::accumulator, 16, 16, 16, float> oacc[2];
#pragma unroll
    for (int j = 0; j < 2; j++) wmma::fill_fragment(oacc[j], 0.f);

    const int ntiles = blockIdx.x + 1;
    for (int kt = 0; kt < ntiles; kt++) {
        const int kb = kt * 64;
        __syncthreads();
#pragma unroll
        for (int s = 0; s < 2; s++) {
            int idx = tid + s * 256;
            int r = idx >> 3, c8 = (idx & 7) * 8;
            size_t g = hb + (size_t)(kb + r) * kD + c8;
            *(uint4*)&Kh[r * 72 + c8] = *(const uint4*)(g_kbh + g);
            *(uint4*)&Kl[r * 72 + c8] = *(const uint4*)(g_kbl + g);
            *(uint4*)&Vh[r * 72 + c8] = *(const uint4*)(g_vbh + g);
            *(uint4*)&Vl[r * 72 + c8] = *(const uint4*)(g_vbl + g);
        }
        __syncthreads();

        // ---- S = Qh Kh + Qh Kl + Ql Kh  (warp tile 16x32)
        wmma::fragment<wmma::accumulator, 16, 16, 16, float> sacc[2];
#pragma unroll
        for (int j = 0; j < 2; j++) wmma::fill_fragment(sacc[j], 0.f);
#pragma unroll
        for (int ks = 0; ks < 4; ks++) {
            wmma::fragment<wmma::matrix_a, 16, 16, 16, __nv_bfloat16,
                           wmma::row_major> ah, al;
            wmma::load_matrix_sync(ah, &Qh[(wm * 16) * 72 + ks * 16], 72);
            wmma::load_matrix_sync(al, &Ql[(wm * 16) * 72 + ks * 16], 72);
#pragma unroll
            for (int j = 0; j < 2; j++) {
                wmma::fragment<wmma::matrix_b, 16, 16, 16, __nv_bfloat16,
                               wmma::col_major> bhf, blf;
                wmma::load_matrix_sync(
                    bhf, &Kh[(wn * 32 + j * 16) * 72 + ks * 16], 72);
                wmma::load_matrix_sync(
                    blf, &Kl[(wn * 32 + j * 16) * 72 + ks * 16], 72);
                wmma::mma_sync(sacc[j], ah, bhf, sacc[j]);
                wmma::mma_sync(sacc[j], ah, blf, sacc[j]);
                wmma::mma_sync(sacc[j], al, bhf, sacc[j]);
            }
        }
#pragma unroll
        for (int j = 0; j < 2; j++)
            wmma::store_matrix_sync(&Ps[(wm * 16) * 68 + wn * 32 + j * 16],
                                    sacc[j], 68, wmma::mem_row_major);
        __syncthreads();

        // ---- masked exp (max-free), row-partial normalizer, P -> hi/lo bf16
        {
            int r = tid >> 2, g = tid & 3;
            int qpos = q0 + r;
            float lsum = 0.f;
#pragma unroll
            for (int i = 0; i < 16; i++) {
                int c = g * 16 + i;
                float s = Ps[r * 68 + c] * 0.125f;
                float p = fast_exp2(s * L2E);
                if (kb + c > qpos) p = 0.f;
                lsum += p;
                __nv_bfloat16 ph = __float2bfloat16(p);
                Pbh[r * 72 + c] = ph;
                Pbl[r * 72 + c] = __float2bfloat16(p - __bfloat162float(ph));
            }
            lp[g * 64 + r] += lsum;
        }
        __syncthreads();

        // ---- O += Ph Vh + Ph Vl + Pl Vh
#pragma unroll
        for (int ks = 0; ks < 4; ks++) {
            wmma::fragment<wmma::matrix_a, 16, 16, 16, __nv_bfloat16,
                           wmma::row_major> ah, al;
            wmma::load_matrix_sync(ah, &Pbh[(wm * 16) * 72 + ks * 16], 72);
            wmma::load_matrix_sync(al, &Pbl[(wm * 16) * 72 + ks * 16], 72);
#pragma unroll
            for (int j = 0; j < 2; j++) {
                wmma::fragment<wmma::matrix_b, 16, 16, 16, __nv_bfloat16,
                               wmma::row_major> bhf, blf;
                wmma::load_matrix_sync(
                    bhf, &Vh[(ks * 16) * 72 + wn * 32 + j * 16], 72);
                wmma::load_matrix_sync(
                    blf, &Vl[(ks * 16) * 72 + wn * 32 + j * 16], 72);
                wmma::mma_sync(oacc[j], ah, bhf, oacc[j]);
                wmma::mma_sync(oacc[j], ah, blf, oacc[j]);
                wmma::mma_sync(oacc[j], al, bhf, oacc[j]);
            }
        }
    }

    // ---- epilogue: O -> smem, normalize rows, write bf16 hi/lo
    __syncthreads();
#pragma unroll
    for (int j = 0; j < 2; j++)
        wmma::store_matrix_sync(&Ps[(wm * 16) * 68 + wn * 32 + j * 16],
                                oacc[j], 68, wmma::mem_row_major);
    __syncthreads();
    {
        int r = tid >> 2, g = tid & 3;
        float lrow = lp[r] + lp[64 + r] + lp[128 + r] + lp[192 + r];
        float inv = 1.f / lrow;
        const int b = bh >> 4, h = bh & 15;
        size_t base = (size_t)(b * kT + q0 + r) * kC + h * kD;
#pragma unroll
        for (int i = 0; i < 16; i++) {
            int c = g * 16 + i;
            float v = Ps[r * 68 + c] * inv;
            __nv_bfloat16 hv = __float2bfloat16(v);
            g_ath[base + c] = hv;
            g_atl[base + c] = __float2bfloat16(v - __bfloat162float(hv));
        }
    }
}

// ===========================================================================
extern "C" void kernel_launch(void* const* d_in, const int* in_sizes, int n_in,
                              void* d_out, int out_size)
{
    const float* x    = (const float*)d_in[0];
    const float* cosp = (const float*)d_in[1];
    const float* sinp = (const float*)d_in[2];
    // d_in[3] = mask (implicit causal)
    const float* Wqkv = (const float*)d_in[4];
    const float* Wout = (const float*)d_in[5];
    float* out = (float*)d_out;

    float* pqkv;
    __half *pxf, *pwqf;
    __nv_bfloat16 *path, *patl, *pwoh, *pwol;
    cudaGetSymbolAddress((void**)&pqkv, g_qkv);
    cudaGetSymbolAddress((void**)&pxf, g_xf);
    cudaGetSymbolAddress((void**)&pwqf, g_wqf);
    cudaGetSymbolAddress((void**)&path, g_ath);
    cudaGetSymbolAddress((void**)&patl, g_atl);
    cudaGetSymbolAddress((void**)&pwoh, g_woh);
    cudaGetSymbolAddress((void**)&pwol, g_wol);

    cudaFuncSetAttribute(gemm_wmma_fp16,
                         cudaFuncAttributeMaxDynamicSharedMemorySize, kGemmSmem16);
    cudaFuncSetAttribute(gemm_wmma_split,
                         cudaFuncAttributeMaxDynamicSharedMemorySize, kGemmSmemBf);
    cudaFuncSetAttribute(flash_wmma2,
                         cudaFuncAttributeMaxDynamicSharedMemorySize, kAttnSmem);

    // 1. convert QKV-GEMM inputs to fp16, out-proj weights to bf16 hi/lo
    cvt_fp16_4<<<(kM * kC / 4 + 255) / 256, 256>>>(x, pxf, kM * kC / 4);
    cvt_fp16_4<<<(kNQKV * kC / 4 + 255) / 256, 256>>>(Wqkv, pwqf, kNQKV * kC / 4);
    cvt_hilo4<<<(kC * kC / 4 + 255) / 256, 256>>>(Wout, pwoh, pwol, kC * kC / 4);

    // 2. QKV projection (single-pass fp16 WMMA — 1/3 the MACs)
    gemm_wmma_fp16<<<dim3(kNQKV / 128, kM / 128), 256, kGemmSmem16>>>(
        pxf, pwqf, pqkv, kNQKV, kC);

    // 3. RoPE + head split -> hi/lo bf16 Q/K/V
    rope_split<<<(kBH * kT * 32) / 256, 256>>>(pqkv, cosp, sinp);

    // 4. split-bf16 WMMA causal attention (writes bf16 hi/lo directly)
    flash_wmma2<<<dim3(kT / 64, kBH), 256, kAttnSmem>>>();

    // 5. output projection (3-pass split-bf16 — precision-critical)
    gemm_wmma_split<<<dim3(kC / 128, kM / 128), 256, kGemmSmemBf>>>(
        path, patl, pwoh, pwol, out, kC, kC);
}